// round 4
// baseline (speedup 1.0000x reference)
#include <cuda_runtime.h>
#include <cuda_fp16.h>
#include <stdint.h>

#define CLS   200
#define DD    768
#define NB    12
#define TILE  128

// smem layout (bytes)
#define WT_PITCH 1552                     // 776 halves per sample row (768 + 8 pad)
#define WT_BYTES (TILE * WT_PITCH)        // 198656
#define LS_OFF   WT_BYTES                 // two 8KB L staging buffers (swizzled)
#define LS_BYTES 8192
#define RS_OFF   (LS_OFF + 2 * LS_BYTES)  // 215040 (128B aligned)
#define RS_BYTES 16384
#define SMEM_TOTAL (RS_OFF + RS_BYTES)    // 231424 <= 232448

// scratch: fp16 pre-swizzled L blocks (lower off-diag, tri-packed) and diag-block inverses
__device__ __align__(16) __half g_Lh[(size_t)CLS * 66 * 4096];
__device__ __align__(16) __half g_Bh[(size_t)CLS * NB * 4096];

__device__ __forceinline__ unsigned swz(unsigned o) { return o ^ ((o >> 3) & 0x70); }

// ---------------------------------------------------------------------------
// P1: convert off-diagonal 64x64 L blocks to fp16, SW128-swizzled, tri-packed
// ---------------------------------------------------------------------------
__global__ void prep_offdiag(const float* __restrict__ L) {
    int t = blockIdx.x;           // 0..65 tri index
    int c = blockIdx.y;
    int bi = 1;
    while (bi * (bi + 1) / 2 <= t) bi++;
    int bk = t - bi * (bi - 1) / 2;

    __half* dst = g_Lh + ((size_t)c * 66 + t) * 4096;
    const float* src = L + ((size_t)c * DD + bi * 64) * DD + bk * 64;

    for (int u = threadIdx.x; u < 512; u += blockDim.x) {
        int r = u >> 3, cg = u & 7;
        const float* p = src + (size_t)r * DD + cg * 8;
        float4 f0 = *(const float4*)p;
        float4 f1 = *(const float4*)(p + 4);
        __half2 p0 = __floats2half2_rn(f0.x, f0.y);
        __half2 p1 = __floats2half2_rn(f0.z, f0.w);
        __half2 p2 = __floats2half2_rn(f1.x, f1.y);
        __half2 p3 = __floats2half2_rn(f1.z, f1.w);
        uint4 v = make_uint4(*(unsigned*)&p0, *(unsigned*)&p1,
                             *(unsigned*)&p2, *(unsigned*)&p3);
        *(uint4*)((char*)dst + swz((unsigned)(r * 128 + cg * 16))) = v;
    }
}

// ---------------------------------------------------------------------------
// P2: invert 64x64 diagonal blocks (fp32 column solves), store fp16 swizzled
// ---------------------------------------------------------------------------
__global__ void prep_diag(const float* __restrict__ L) {
    int bi = blockIdx.x;
    int c  = blockIdx.y;
    __shared__ float Ls2[64][65];
    __shared__ float Z[64][65];
    int j = threadIdx.x;          // 64 threads, one column each

    const float* src = L + ((size_t)c * DD + bi * 64) * DD + bi * 64;
    for (int u = j; u < 4096; u += 64)
        Ls2[u >> 6][u & 63] = src[(size_t)(u >> 6) * DD + (u & 63)];
    __syncthreads();

    // forward substitution for column j of inv(L_ii); thread-private column
    for (int k = 0; k < 64; k++) {
        float s = (k == j) ? 1.f : 0.f;
        if (k > j) {
            float s0 = 0.f, s1 = 0.f, s2 = 0.f, s3 = 0.f;
            int m = j;
            for (; m + 4 <= k; m += 4) {
                s0 += Ls2[k][m]     * Z[m][j];
                s1 += Ls2[k][m + 1] * Z[m + 1][j];
                s2 += Ls2[k][m + 2] * Z[m + 2][j];
                s3 += Ls2[k][m + 3] * Z[m + 3][j];
            }
            for (; m < k; m++) s0 += Ls2[k][m] * Z[m][j];
            s -= (s0 + s1) + (s2 + s3);
        }
        Z[k][j] = (k >= j) ? s / Ls2[k][k] : 0.f;
    }

    __half* dst = g_Bh + ((size_t)c * NB + bi) * 4096;
    for (int k = 0; k < 64; k++)
        *(__half*)((char*)dst + swz((unsigned)(k * 128 + j * 2))) = __float2half(Z[k][j]);
}

// ---------------------------------------------------------------------------
// MMA / ldmatrix / cp.async helpers
// ---------------------------------------------------------------------------
__device__ __forceinline__ void ldsm_x4(uint32_t a, uint32_t& r0, uint32_t& r1,
                                        uint32_t& r2, uint32_t& r3) {
    asm volatile("ldmatrix.sync.aligned.m8n8.x4.shared.b16 {%0,%1,%2,%3}, [%4];\n"
                 : "=r"(r0), "=r"(r1), "=r"(r2), "=r"(r3) : "r"(a));
}
__device__ __forceinline__ void mma16816(float* d, uint32_t a0, uint32_t a1,
                                         uint32_t a2, uint32_t a3,
                                         uint32_t b0, uint32_t b1) {
    asm volatile(
        "mma.sync.aligned.m16n8k16.row.col.f32.f16.f16.f32 "
        "{%0,%1,%2,%3}, {%4,%5,%6,%7}, {%8,%9}, {%0,%1,%2,%3};\n"
        : "+f"(d[0]), "+f"(d[1]), "+f"(d[2]), "+f"(d[3])
        : "r"(a0), "r"(a1), "r"(a2), "r"(a3), "r"(b0), "r"(b1));
}
__device__ __forceinline__ void cpasync16(uint32_t dst, const void* src) {
    asm volatile("cp.async.cg.shared.global [%0], [%1], 16;\n" :: "r"(dst), "l"(src));
}
#define CP_COMMIT()  asm volatile("cp.async.commit_group;\n")
#define CP_WAIT(n)   asm volatile("cp.async.wait_group %0;\n" :: "n"(n))

__device__ __forceinline__ void stage_block(uint32_t smem_dst, const __half* gsrc, int tid) {
    cpasync16(smem_dst + tid * 16,        (const char*)gsrc + tid * 16);
    cpasync16(smem_dst + 4096 + tid * 16, (const char*)gsrc + 4096 + tid * 16);
}

// ---------------------------------------------------------------------------
// Main kernel: per (class, 128-sample tile) blocked forward substitution
//   y_i = Linv_ii (w_i - sum_{k<i} L_ik y_k),  dist = sum y^2
// ---------------------------------------------------------------------------
extern "C" __global__ void __launch_bounds__(256, 1)
fecam_main(const float* __restrict__ x, const float* __restrict__ mu,
           const float* __restrict__ stdv, const float* __restrict__ logdetR,
           float* __restrict__ out)
{
    extern __shared__ __align__(16) char sm[];
    const int tid  = threadIdx.x;
    const int lane = tid & 31;
    const int w    = tid >> 5;
    const int wi   = w >> 1;       // 0..3 : 16-row m tile (features within block)
    const int wn   = w & 1;        // 0..1 : 64-col n tile (samples)
    const int tile = blockIdx.x;   // 0..7
    const int c    = blockIdx.y;   // 0..199

    const uint32_t smb = (uint32_t)__cvta_generic_to_shared(sm);
    char* smc = sm;

    // ---- Phase 1: build Wt[s][j] = (x - mu)/max(std,eps) in fp16 ----
    {
        const float* xp  = x + (size_t)tile * TILE * DD;
        const float* mup = mu + (size_t)c * DD;
        const float* sp  = stdv + (size_t)c * DD;
        for (int idx = tid; idx < TILE * (DD / 4); idx += 256) {
            int s  = idx / (DD / 4);
            int j4 = idx - s * (DD / 4);
            float4 xv = *(const float4*)(xp + (size_t)s * DD + j4 * 4);
            float4 mv = *(const float4*)(mup + j4 * 4);
            float4 sv = *(const float4*)(sp + j4 * 4);
            float w0 = (xv.x - mv.x) / fmaxf(sv.x, 1e-6f);
            float w1 = (xv.y - mv.y) / fmaxf(sv.y, 1e-6f);
            float w2 = (xv.z - mv.z) / fmaxf(sv.z, 1e-6f);
            float w3 = (xv.w - mv.w) / fmaxf(sv.w, 1e-6f);
            __half2 h0 = __floats2half2_rn(w0, w1);
            __half2 h1 = __floats2half2_rn(w2, w3);
            *(uint2*)(smc + s * WT_PITCH + j4 * 8) =
                make_uint2(*(unsigned*)&h0, *(unsigned*)&h1);
        }
    }
    __syncthreads();

    float dcol[8][2];
#pragma unroll
    for (int f = 0; f < 8; f++) { dcol[f][0] = 0.f; dcol[f][1] = 0.f; }

    const uint32_t ls0 = smb + LS_OFF;
    const uint32_t ls1 = smb + LS_OFF + LS_BYTES;
    const uint32_t rsb = smb + RS_OFF;

    for (int bi = 0; bi < NB; bi++) {
        float acc[8][4];
#pragma unroll
        for (int f = 0; f < 8; f++) {
            acc[f][0] = acc[f][1] = acc[f][2] = acc[f][3] = 0.f;
        }

        const __half* Lrow = g_Lh + ((size_t)c * 66 + (size_t)(bi * (bi - 1) / 2)) * 4096;

        // ---- off-diagonal accumulation: acc = sum_{k<bi} L[bi][k] * y_k ----
        if (bi > 0) {
            stage_block(ls0, Lrow, tid);
            CP_COMMIT();
            for (int kb = 0; kb < bi; kb++) {
                if (kb + 1 < bi) {
                    stage_block((kb & 1) ? ls0 : ls1, Lrow + (size_t)(kb + 1) * 4096, tid);
                    CP_COMMIT();
                    CP_WAIT(1);
                } else {
                    CP_WAIT(0);
                }
                __syncthreads();
                uint32_t buf = (kb & 1) ? ls1 : ls0;
#pragma unroll
                for (int ks = 0; ks < 4; ks++) {
                    uint32_t a0, a1, a2, a3;
                    {
                        int row  = 16 * wi + (lane & 15);
                        int colh = ks * 16 + ((lane >> 4) << 3);
                        ldsm_x4(buf + swz((unsigned)(row * 128 + colh * 2)), a0, a1, a2, a3);
                    }
                    int jb = kb * 64 + ks * 16;
#pragma unroll
                    for (int g = 0; g < 4; g++) {
                        uint32_t b0, b1, b2, b3;
                        // B operand: Wt is n-major (k contiguous) -> NON-trans ldmatrix
                        int n  = 64 * wn + 16 * g + (lane & 7) + ((lane >> 4) << 3);
                        int kh = jb + (((lane >> 3) & 1) << 3);
                        ldsm_x4(smb + (unsigned)(n * WT_PITCH + kh * 2), b0, b1, b2, b3);
                        mma16816(acc[2 * g],     a0, a1, a2, a3, b0, b1);
                        mma16816(acc[2 * g + 1], a0, a1, a2, a3, b2, b3);
                    }
                }
                __syncthreads();
            }
        }

        // ---- stage diag inverse block (overlaps resid computation) ----
        stage_block(ls0, g_Bh + ((size_t)c * NB + bi) * 4096, tid);
        CP_COMMIT();

        // ---- resid = w_bi - acc -> Rs (fp16, swizzled, sample-major 128B rows) ----
        {
            int r0  = 16 * wi + (lane >> 2);
            int jb2 = 64 * bi;
#pragma unroll
            for (int f = 0; f < 8; f++) {
                int s0 = 64 * wn + 8 * f + 2 * (lane & 3);
                float w00 = __half2float(*(const __half*)(smc + s0 * WT_PITCH + (jb2 + r0) * 2));
                float w01 = __half2float(*(const __half*)(smc + (s0 + 1) * WT_PITCH + (jb2 + r0) * 2));
                float w10 = __half2float(*(const __half*)(smc + s0 * WT_PITCH + (jb2 + r0 + 8) * 2));
                float w11 = __half2float(*(const __half*)(smc + (s0 + 1) * WT_PITCH + (jb2 + r0 + 8) * 2));
                *(__half*)(smc + RS_OFF + swz((unsigned)(s0 * 128 + r0 * 2)))             = __float2half(w00 - acc[f][0]);
                *(__half*)(smc + RS_OFF + swz((unsigned)((s0 + 1) * 128 + r0 * 2)))       = __float2half(w01 - acc[f][1]);
                *(__half*)(smc + RS_OFF + swz((unsigned)(s0 * 128 + (r0 + 8) * 2)))       = __float2half(w10 - acc[f][2]);
                *(__half*)(smc + RS_OFF + swz((unsigned)((s0 + 1) * 128 + (r0 + 8) * 2))) = __float2half(w11 - acc[f][3]);
            }
        }
        CP_WAIT(0);
        __syncthreads();

        // ---- y_bi = B_ii * resid ----
        float y[8][4];
#pragma unroll
        for (int f = 0; f < 8; f++) {
            y[f][0] = y[f][1] = y[f][2] = y[f][3] = 0.f;
        }
#pragma unroll
        for (int ks = 0; ks < 4; ks++) {
            uint32_t a0, a1, a2, a3;
            {
                int row  = 16 * wi + (lane & 15);
                int colh = ks * 16 + ((lane >> 4) << 3);
                ldsm_x4(ls0 + swz((unsigned)(row * 128 + colh * 2)), a0, a1, a2, a3);
            }
#pragma unroll
            for (int g = 0; g < 4; g++) {
                uint32_t b0, b1, b2, b3;
                // Rs is n-major (k contiguous, swizzled) -> NON-trans ldmatrix
                int n  = 64 * wn + 16 * g + (lane & 7) + ((lane >> 4) << 3);
                int kh = ks * 16 + (((lane >> 3) & 1) << 3);
                ldsm_x4(rsb + swz((unsigned)(n * 128 + kh * 2)), b0, b1, b2, b3);
                mma16816(y[2 * g],     a0, a1, a2, a3, b0, b1);
                mma16816(y[2 * g + 1], a0, a1, a2, a3, b2, b3);
            }
        }

        // ---- dist += y^2 ; write y back into Wt block bi (fp16) ----
        {
            int r0  = 16 * wi + (lane >> 2);
            int jb2 = 64 * bi;
#pragma unroll
            for (int f = 0; f < 8; f++) {
                int s0 = 64 * wn + 8 * f + 2 * (lane & 3);
                dcol[f][0] += y[f][0] * y[f][0] + y[f][2] * y[f][2];
                dcol[f][1] += y[f][1] * y[f][1] + y[f][3] * y[f][3];
                *(__half*)(smc + s0 * WT_PITCH + (jb2 + r0) * 2)           = __float2half(y[f][0]);
                *(__half*)(smc + (s0 + 1) * WT_PITCH + (jb2 + r0) * 2)     = __float2half(y[f][1]);
                *(__half*)(smc + s0 * WT_PITCH + (jb2 + r0 + 8) * 2)       = __float2half(y[f][2]);
                *(__half*)(smc + (s0 + 1) * WT_PITCH + (jb2 + r0 + 8) * 2) = __float2half(y[f][3]);
            }
        }
        __syncthreads();
    }

    // ---- deterministic cross-warp reduction of dist, write logits ----
    float* rf = (float*)(smc + RS_OFF);
    {
        int contrib = wi * 8 + (lane >> 2);
#pragma unroll
        for (int f = 0; f < 8; f++) {
            int s0 = 64 * wn + 8 * f + 2 * (lane & 3);
            rf[s0 * 32 + contrib]       = dcol[f][0];
            rf[(s0 + 1) * 32 + contrib] = dcol[f][1];
        }
    }
    __syncthreads();
    if (tid < TILE) {
        float s = 0.f;
#pragma unroll
        for (int u = 0; u < 32; u++) s += rf[tid * 32 + u];
        float lg = -0.5f * s - 0.5f * logdetR[c];
        out[(size_t)(tile * TILE + tid) * CLS + c] = lg;
    }
}

// ---------------------------------------------------------------------------
extern "C" void kernel_launch(void* const* d_in, const int* in_sizes, int n_in,
                              void* d_out, int out_size) {
    const float* x       = (const float*)d_in[0];
    const float* mu      = (const float*)d_in[1];
    const float* stdv    = (const float*)d_in[2];
    const float* L       = (const float*)d_in[3];
    const float* logdetR = (const float*)d_in[4];
    float* out = (float*)d_out;

    prep_offdiag<<<dim3(66, CLS), 256>>>(L);
    prep_diag<<<dim3(NB, CLS), 64>>>(L);

    cudaFuncSetAttribute(fecam_main, cudaFuncAttributeMaxDynamicSharedMemorySize, SMEM_TOTAL);
    fecam_main<<<dim3(8, CLS), 256, SMEM_TOTAL>>>(x, mu, stdv, logdetR, out);
}

// round 9
// speedup vs baseline: 1.1021x; 1.1021x over previous
#include <cuda_runtime.h>
#include <cuda_fp16.h>
#include <stdint.h>

#define CLS   200
#define DD    768
#define NB    12
#define TILE  128

// smem layout (bytes)
#define WT_PITCH 1552                     // 776 halves per sample row (768 + 8 pad)
#define WT_BYTES (TILE * WT_PITCH)        // 198656
#define LS_OFF   WT_BYTES                 // two 8KB L staging buffers (swizzled)
#define LS_BYTES 8192
#define RF_OFF   (LS_OFF + 2 * LS_BYTES)  // 215040: float reduction scratch
#define RF_BYTES 16384
#define SMEM_TOTAL (RF_OFF + RF_BYTES)    // 231424 <= 232448

// scratch: fp16 pre-swizzled L blocks (lower off-diag, tri-packed) and diag-block inverses
__device__ __align__(16) __half g_Lh[(size_t)CLS * 66 * 4096];
__device__ __align__(16) __half g_Bh[(size_t)CLS * NB * 4096];

__device__ __forceinline__ unsigned swz(unsigned o) { return o ^ ((o >> 3) & 0x70); }

// ---------------------------------------------------------------------------
// Merged prep: blocks x<66 convert off-diag L blocks (fp16, SW128 swizzled);
// blocks x>=66 invert 64x64 diagonal blocks (fp32 solves) -> fp16 swizzled.
// One kernel => 2 launches per replay => ncu -s 5 lands on fecam_main.
// ---------------------------------------------------------------------------
__global__ void prep_all(const float* __restrict__ L) {
    __shared__ float Ls2[64][65];
    __shared__ float Z[64][65];
    int bx = blockIdx.x;
    int c  = blockIdx.y;

    if (bx < 66) {
        int t = bx;                 // tri index
        int bi = 1;
        while (bi * (bi + 1) / 2 <= t) bi++;
        int bk = t - bi * (bi - 1) / 2;

        __half* dst = g_Lh + ((size_t)c * 66 + t) * 4096;
        const float* src = L + ((size_t)c * DD + bi * 64) * DD + bk * 64;

        for (int u = threadIdx.x; u < 512; u += blockDim.x) {
            int r = u >> 3, cg = u & 7;
            const float* p = src + (size_t)r * DD + cg * 8;
            float4 f0 = *(const float4*)p;
            float4 f1 = *(const float4*)(p + 4);
            __half2 p0 = __floats2half2_rn(f0.x, f0.y);
            __half2 p1 = __floats2half2_rn(f0.z, f0.w);
            __half2 p2 = __floats2half2_rn(f1.x, f1.y);
            __half2 p3 = __floats2half2_rn(f1.z, f1.w);
            uint4 v = make_uint4(*(unsigned*)&p0, *(unsigned*)&p1,
                                 *(unsigned*)&p2, *(unsigned*)&p3);
            *(uint4*)((char*)dst + swz((unsigned)(r * 128 + cg * 16))) = v;
        }
    } else {
        int bi = bx - 66;
        const float* src = L + ((size_t)c * DD + bi * 64) * DD + bi * 64;
        for (int u = threadIdx.x; u < 4096; u += blockDim.x)
            Ls2[u >> 6][u & 63] = src[(size_t)(u >> 6) * DD + (u & 63)];
        __syncthreads();

        int j = threadIdx.x;        // thread-private column solve
        if (j < 64) {
            for (int k = 0; k < 64; k++) {
                float s = (k == j) ? 1.f : 0.f;
                if (k > j) {
                    float s0 = 0.f, s1 = 0.f, s2 = 0.f, s3 = 0.f;
                    int m = j;
                    for (; m + 4 <= k; m += 4) {
                        s0 += Ls2[k][m]     * Z[m][j];
                        s1 += Ls2[k][m + 1] * Z[m + 1][j];
                        s2 += Ls2[k][m + 2] * Z[m + 2][j];
                        s3 += Ls2[k][m + 3] * Z[m + 3][j];
                    }
                    for (; m < k; m++) s0 += Ls2[k][m] * Z[m][j];
                    s -= (s0 + s1) + (s2 + s3);
                }
                Z[k][j] = (k >= j) ? s / Ls2[k][k] : 0.f;
            }
            __half* dst = g_Bh + ((size_t)c * NB + bi) * 4096;
            for (int k = 0; k < 64; k++)
                *(__half*)((char*)dst + swz((unsigned)(k * 128 + j * 2))) = __float2half(Z[k][j]);
        }
    }
}

// ---------------------------------------------------------------------------
// MMA / ldmatrix / cp.async helpers
// ---------------------------------------------------------------------------
__device__ __forceinline__ void ldsm_x4(uint32_t a, uint32_t& r0, uint32_t& r1,
                                        uint32_t& r2, uint32_t& r3) {
    asm volatile("ldmatrix.sync.aligned.m8n8.x4.shared.b16 {%0,%1,%2,%3}, [%4];\n"
                 : "=r"(r0), "=r"(r1), "=r"(r2), "=r"(r3) : "r"(a));
}
__device__ __forceinline__ void mma16816(float* d, uint32_t a0, uint32_t a1,
                                         uint32_t a2, uint32_t a3,
                                         uint32_t b0, uint32_t b1) {
    asm volatile(
        "mma.sync.aligned.m16n8k16.row.col.f32.f16.f16.f32 "
        "{%0,%1,%2,%3}, {%4,%5,%6,%7}, {%8,%9}, {%0,%1,%2,%3};\n"
        : "+f"(d[0]), "+f"(d[1]), "+f"(d[2]), "+f"(d[3])
        : "r"(a0), "r"(a1), "r"(a2), "r"(a3), "r"(b0), "r"(b1));
}
__device__ __forceinline__ void cpasync16(uint32_t dst, const void* src) {
    asm volatile("cp.async.cg.shared.global [%0], [%1], 16;\n" :: "r"(dst), "l"(src));
}
#define CP_COMMIT()  asm volatile("cp.async.commit_group;\n")
#define CP_WAIT(n)   asm volatile("cp.async.wait_group %0;\n" :: "n"(n))

// 512 threads: one 16B cp.async each covers 8KB
__device__ __forceinline__ void stage_block(uint32_t smem_dst, const __half* gsrc, int tid) {
    cpasync16(smem_dst + tid * 16, (const char*)gsrc + tid * 16);
}

// ---------------------------------------------------------------------------
// Main kernel: per (class, 128-sample tile) blocked forward substitution
//   y_i = Linv_ii (w_i - sum_{k<i} L_ik y_k),  dist = sum y^2
// 512 threads = 16 warps: wi = warp>>2 (m 16-row tile), wn = warp&3 (32-sample slice)
// ---------------------------------------------------------------------------
extern "C" __global__ void __launch_bounds__(512, 1)
fecam_main(const float* __restrict__ x, const float* __restrict__ mu,
           const float* __restrict__ stdv, const float* __restrict__ logdetR,
           float* __restrict__ out)
{
    extern __shared__ __align__(16) char sm[];
    const int tid  = threadIdx.x;
    const int lane = tid & 31;
    const int w    = tid >> 5;
    const int wi   = w >> 2;       // 0..3 : 16-row m tile (features within block)
    const int wn   = w & 3;        // 0..3 : 32-col n tile (samples)
    const int tile = blockIdx.x;   // 0..7
    const int c    = blockIdx.y;   // 0..199

    const uint32_t smb = (uint32_t)__cvta_generic_to_shared(sm);
    char* smc = sm;

    // ---- Phase 1: build Wt[s][j] = (x - mu)/max(std,eps) in fp16 ----
    {
        const float* xp  = x + (size_t)tile * TILE * DD;
        const float* mup = mu + (size_t)c * DD;
        const float* sp  = stdv + (size_t)c * DD;
        for (int idx = tid; idx < TILE * (DD / 4); idx += 512) {
            int s  = idx / (DD / 4);
            int j4 = idx - s * (DD / 4);
            float4 xv = *(const float4*)(xp + (size_t)s * DD + j4 * 4);
            float4 mv = *(const float4*)(mup + j4 * 4);
            float4 sv = *(const float4*)(sp + j4 * 4);
            float w0 = (xv.x - mv.x) / fmaxf(sv.x, 1e-6f);
            float w1 = (xv.y - mv.y) / fmaxf(sv.y, 1e-6f);
            float w2 = (xv.z - mv.z) / fmaxf(sv.z, 1e-6f);
            float w3 = (xv.w - mv.w) / fmaxf(sv.w, 1e-6f);
            __half2 h0 = __floats2half2_rn(w0, w1);
            __half2 h1 = __floats2half2_rn(w2, w3);
            *(uint2*)(smc + s * WT_PITCH + j4 * 8) =
                make_uint2(*(unsigned*)&h0, *(unsigned*)&h1);
        }
    }
    __syncthreads();

    float dcol[4][2];
#pragma unroll
    for (int f = 0; f < 4; f++) { dcol[f][0] = 0.f; dcol[f][1] = 0.f; }

    const uint32_t lsb[2] = { smb + LS_OFF, smb + LS_OFF + LS_BYTES };

    // A-fragment address components (same for every 64x64 block)
    const int arow  = 16 * wi + (lane & 15);
    const int acolh = (lane >> 4) << 3;
    // B-fragment address components (Wt, n-major k-contiguous, non-trans ldsm)
    const int bn0 = 32 * wn + (lane & 7) + ((lane >> 4) << 3);
    const int bkh = ((lane >> 3) & 1) << 3;

    for (int bi = 0; bi < NB; bi++) {
        float acc[4][4];
#pragma unroll
        for (int f = 0; f < 4; f++) {
            acc[f][0] = acc[f][1] = acc[f][2] = acc[f][3] = 0.f;
        }

        const __half* Lrow = g_Lh + ((size_t)c * 66 + (size_t)(bi * (bi - 1) / 2)) * 4096;
        const __half* Bblk = g_Bh + ((size_t)c * NB + bi) * 4096;

        if (bi == 0) {
            stage_block(lsb[0], Bblk, tid);   // diag inverse straight into buf0
            CP_COMMIT();
        } else {
            stage_block(lsb[0], Lrow, tid);   // L[bi][0]
            CP_COMMIT();
            // ---- off-diag accumulation: acc = sum_{k<bi} L[bi][k] * y_k ----
            for (int kb = 0; kb < bi; kb++) {
                CP_WAIT(0);
                __syncthreads();              // stage(kb) visible; prev reads of target buf done
                if (kb + 1 < bi)
                    stage_block(lsb[(kb + 1) & 1], Lrow + (size_t)(kb + 1) * 4096, tid);
                else
                    stage_block(lsb[bi & 1], Bblk, tid);   // diag inverse into idle buf
                CP_COMMIT();
                uint32_t buf = lsb[kb & 1];
#pragma unroll
                for (int ks = 0; ks < 4; ks++) {
                    uint32_t a0, a1, a2, a3;
                    ldsm_x4(buf + swz((unsigned)(arow * 128 + (ks * 16 + acolh) * 2)),
                            a0, a1, a2, a3);
                    int jb = kb * 64 + ks * 16;
#pragma unroll
                    for (int g = 0; g < 2; g++) {
                        uint32_t b0, b1, b2, b3;
                        int n  = bn0 + 16 * g;
                        int kh = jb + bkh;
                        ldsm_x4(smb + (unsigned)(n * WT_PITCH + kh * 2), b0, b1, b2, b3);
                        mma16816(acc[2 * g],     a0, a1, a2, a3, b0, b1);
                        mma16816(acc[2 * g + 1], a0, a1, a2, a3, b2, b3);
                    }
                }
            }
        }

        // ---- resid = w_bi - acc, written back into Wt block bi (fp16) ----
        const int r0  = 16 * wi + (lane >> 2);
        const int jb2 = 64 * bi;
        if (bi > 0) {
#pragma unroll
            for (int f = 0; f < 4; f++) {
                int s0 = 32 * wn + 8 * f + 2 * (lane & 3);
                __half* p00 = (__half*)(smc + s0 * WT_PITCH + (jb2 + r0) * 2);
                __half* p01 = (__half*)(smc + (s0 + 1) * WT_PITCH + (jb2 + r0) * 2);
                __half* p10 = (__half*)(smc + s0 * WT_PITCH + (jb2 + r0 + 8) * 2);
                __half* p11 = (__half*)(smc + (s0 + 1) * WT_PITCH + (jb2 + r0 + 8) * 2);
                *p00 = __float2half(__half2float(*p00) - acc[f][0]);
                *p01 = __float2half(__half2float(*p01) - acc[f][1]);
                *p10 = __float2half(__half2float(*p10) - acc[f][2]);
                *p11 = __float2half(__half2float(*p11) - acc[f][3]);
            }
        }
        CP_WAIT(0);
        __syncthreads();                      // diag block staged+visible; resid visible

        // ---- y_bi = Binv_ii * resid (resid read from Wt block bi) ----
        float y[4][4];
#pragma unroll
        for (int f = 0; f < 4; f++) {
            y[f][0] = y[f][1] = y[f][2] = y[f][3] = 0.f;
        }
        uint32_t bufD = lsb[bi & 1];
#pragma unroll
        for (int ks = 0; ks < 4; ks++) {
            uint32_t a0, a1, a2, a3;
            ldsm_x4(bufD + swz((unsigned)(arow * 128 + (ks * 16 + acolh) * 2)),
                    a0, a1, a2, a3);
#pragma unroll
            for (int g = 0; g < 2; g++) {
                uint32_t b0, b1, b2, b3;
                int n  = bn0 + 16 * g;
                int kh = jb2 + ks * 16 + bkh;
                ldsm_x4(smb + (unsigned)(n * WT_PITCH + kh * 2), b0, b1, b2, b3);
                mma16816(y[2 * g],     a0, a1, a2, a3, b0, b1);
                mma16816(y[2 * g + 1], a0, a1, a2, a3, b2, b3);
            }
        }

        // ---- dist += y^2 ; write y back into Wt block bi (fp16) ----
#pragma unroll
        for (int f = 0; f < 4; f++) {
            int s0 = 32 * wn + 8 * f + 2 * (lane & 3);
            dcol[f][0] += y[f][0] * y[f][0] + y[f][2] * y[f][2];
            dcol[f][1] += y[f][1] * y[f][1] + y[f][3] * y[f][3];
            *(__half*)(smc + s0 * WT_PITCH + (jb2 + r0) * 2)           = __float2half(y[f][0]);
            *(__half*)(smc + (s0 + 1) * WT_PITCH + (jb2 + r0) * 2)     = __float2half(y[f][1]);
            *(__half*)(smc + s0 * WT_PITCH + (jb2 + r0 + 8) * 2)       = __float2half(y[f][2]);
            *(__half*)(smc + (s0 + 1) * WT_PITCH + (jb2 + r0 + 8) * 2) = __float2half(y[f][3]);
        }
        __syncthreads();                      // y visible before next bi's B-reads
    }

    // ---- deterministic cross-warp reduction of dist, write logits ----
    float* rf = (float*)(smc + RF_OFF);
    {
        int contrib = wi * 8 + (lane >> 2);
#pragma unroll
        for (int f = 0; f < 4; f++) {
            int s0 = 32 * wn + 8 * f + 2 * (lane & 3);
            rf[s0 * 32 + contrib]       = dcol[f][0];
            rf[(s0 + 1) * 32 + contrib] = dcol[f][1];
        }
    }
    __syncthreads();
    if (tid < TILE) {
        float s = 0.f;
#pragma unroll
        for (int u = 0; u < 32; u++) s += rf[tid * 32 + u];
        float lg = -0.5f * s - 0.5f * logdetR[c];
        out[(size_t)(tile * TILE + tid) * CLS + c] = lg;
    }
}

// ---------------------------------------------------------------------------
extern "C" void kernel_launch(void* const* d_in, const int* in_sizes, int n_in,
                              void* d_out, int out_size) {
    const float* x       = (const float*)d_in[0];
    const float* mu      = (const float*)d_in[1];
    const float* stdv    = (const float*)d_in[2];
    const float* L       = (const float*)d_in[3];
    const float* logdetR = (const float*)d_in[4];
    float* out = (float*)d_out;

    prep_all<<<dim3(78, CLS), 256>>>(L);

    cudaFuncSetAttribute(fecam_main, cudaFuncAttributeMaxDynamicSharedMemorySize, SMEM_TOTAL);
    fecam_main<<<dim3(8, CLS), 512, SMEM_TOTAL>>>(x, mu, stdv, logdetR, out);
}